// round 1
// baseline (speedup 1.0000x reference)
#include <cuda_runtime.h>
#include <math.h>

#define NS 3
#define SYM 512
#define FD 20
#define NLIN 11
#define NOUT 9
#define HH 2048
#define HIN (NS*SYM*NOUT)   /* 13824 */
#define NO (NS*SYM)         /* 1536 */
#define EPSF 1e-9f

// ---------------- device scratch (no allocations allowed) ----------------
__device__ float g_v[HIN];
__device__ float g_gates[3*HH];
__device__ float g_h[HH];
__device__ float g_o[NO];

// ---------------- front end: inorm -> DFT -> bilinear -> leaky -> softmax(NS) ----------------
__global__ __launch_bounds__(128) void k_front(const float* __restrict__ wax,
                                               const float* __restrict__ blw,
                                               const float* __restrict__ blb) {
    int s = blockIdx.x;           // 0..511
    int tid = threadIdx.x;
    int warp = tid >> 5, lane = tid & 31;

    __shared__ float sh_xn[NS][FD];
    __shared__ float sh_re[NS][NLIN], sh_im[NS][NLIN];
    __shared__ float sh_z[NS][NOUT];

    if (warp < NS) {
        int b = warp;
        float x = 0.f;
        if (lane < FD) x = wax[(b*SYM + s)*FD + lane];
        float sum = x, sq = x*x;
        #pragma unroll
        for (int o = 16; o > 0; o >>= 1) {
            sum += __shfl_xor_sync(0xffffffffu, sum, o);
            sq  += __shfl_xor_sync(0xffffffffu, sq,  o);
        }
        float m = sum * (1.0f/FD);
        float var = sq * (1.0f/FD) - m*m;
        float r = rsqrtf(var + EPSF);
        if (lane < FD) sh_xn[b][lane] = (x - m) * r;
        __syncwarp();

        if (lane < NLIN) {
            float re = 0.f, im = 0.f;
            #pragma unroll
            for (int f = 0; f < FD; f++) {
                float sn, cs;
                sincospif((float)(lane*f) * 0.1f, &sn, &cs); // 2*pi*k*f/20 = pi*(k*f/10)
                float xv = sh_xn[b][f];
                re += xv * cs;
                im -= xv * sn;
            }
            sh_re[b][lane] = re;
            sh_im[b][lane] = im;
        }
        __syncwarp();

        if (lane < NOUT) {
            int k = lane;
            float z = blb[k];
            #pragma unroll
            for (int i = 0; i < NLIN; i++) {
                float t = 0.f;
                #pragma unroll
                for (int j = 0; j < NLIN; j++)
                    t += blw[(k*NLIN + i)*NLIN + j] * sh_im[b][j];
                z += sh_re[b][i] * t;
            }
            z = (z >= 0.f) ? z : 0.01f*z;   // leaky_relu
            sh_z[b][k] = z;
        }
    }
    __syncthreads();

    if (tid < NOUT) {
        int k = tid;
        float z0 = sh_z[0][k], z1 = sh_z[1][k], z2 = sh_z[2][k];
        float m = fmaxf(z0, fmaxf(z1, z2));
        float e0 = expf(z0-m), e1 = expf(z1-m), e2 = expf(z2-m);
        float inv = 1.f/(e0+e1+e2);
        g_v[s*(NS*NOUT) + 0*NOUT + k] = e0*inv;
        g_v[s*(NS*NOUT) + 1*NOUT + k] = e1*inv;
        g_v[s*(NS*NOUT) + 2*NOUT + k] = e2*inv;
    }
}

// ---------------- gate matvec: 4 rows per block, skip f-gate ----------------
template<int NT>
__global__ __launch_bounds__(NT) void k_gates4(const float* __restrict__ W,
                                               const float* __restrict__ x,
                                               const float* __restrict__ b_ih,
                                               const float* __restrict__ b_hh,
                                               float* __restrict__ gates, int n) {
    const int task0 = blockIdx.x * 4;        // tasks 0..3*HH-1, task -> (g3, j)
    const int n4 = n >> 2;
    const float4* xv = (const float4*)x;

    const float4* Wr[4];
    #pragma unroll
    for (int r = 0; r < 4; r++) {
        int task = task0 + r;
        int g3 = task / HH;
        int j  = task - g3*HH;
        int gate = (g3 == 0) ? 0 : (g3 + 1);   // 0 -> i, 1 -> g(row 2H), 2 -> o(row 3H)
        Wr[r] = (const float4*)(W + (size_t)(gate*HH + j) * n);
    }

    float acc[4] = {0.f, 0.f, 0.f, 0.f};
    for (int t = threadIdx.x; t < n4; t += NT) {
        float4 v = xv[t];
        #pragma unroll
        for (int r = 0; r < 4; r++) {
            float4 w = Wr[r][t];
            acc[r] += w.x*v.x + w.y*v.y + w.z*v.z + w.w*v.w;
        }
    }

    __shared__ float sred[4][NT/32];
    #pragma unroll
    for (int r = 0; r < 4; r++) {
        float a = acc[r];
        #pragma unroll
        for (int o = 16; o > 0; o >>= 1) a += __shfl_xor_sync(0xffffffffu, a, o);
        if ((threadIdx.x & 31) == 0) sred[r][threadIdx.x >> 5] = a;
    }
    __syncthreads();
    if (threadIdx.x < 4) {
        int r = threadIdx.x;
        float a = 0.f;
        #pragma unroll
        for (int w = 0; w < NT/32; w++) a += sred[r][w];
        int task = task0 + r;
        int g3 = task / HH;
        int j  = task - g3*HH;
        int gate = (g3 == 0) ? 0 : (g3 + 1);
        int row = gate*HH + j;
        gates[task] = a + b_ih[row] + b_hh[row];
    }
}

// ---------------- LSTM activation (c0 = 0 => f-gate irrelevant) ----------------
__global__ __launch_bounds__(256) void k_act(const float* __restrict__ gates,
                                             float* __restrict__ h) {
    int j = blockIdx.x*blockDim.x + threadIdx.x;
    if (j < HH) {
        float gi = gates[j], gg = gates[HH + j], go = gates[2*HH + j];
        float si = 1.f/(1.f + expf(-gi));
        float so = 1.f/(1.f + expf(-go));
        float c  = si * tanhf(gg);
        h[j] = so * tanhf(c);
    }
}

// ---------------- linear head: 4 rows per block ----------------
template<int NT>
__global__ __launch_bounds__(NT) void k_lin4(const float* __restrict__ W,
                                             const float* __restrict__ x,
                                             const float* __restrict__ b,
                                             float* __restrict__ out, int n) {
    const int row0 = blockIdx.x * 4;
    const int n4 = n >> 2;
    const float4* xv = (const float4*)x;

    const float4* Wr[4];
    #pragma unroll
    for (int r = 0; r < 4; r++)
        Wr[r] = (const float4*)(W + (size_t)(row0 + r) * n);

    float acc[4] = {0.f, 0.f, 0.f, 0.f};
    for (int t = threadIdx.x; t < n4; t += NT) {
        float4 v = xv[t];
        #pragma unroll
        for (int r = 0; r < 4; r++) {
            float4 w = Wr[r][t];
            acc[r] += w.x*v.x + w.y*v.y + w.z*v.z + w.w*v.w;
        }
    }

    __shared__ float sred[4][NT/32];
    #pragma unroll
    for (int r = 0; r < 4; r++) {
        float a = acc[r];
        #pragma unroll
        for (int o = 16; o > 0; o >>= 1) a += __shfl_xor_sync(0xffffffffu, a, o);
        if ((threadIdx.x & 31) == 0) sred[r][threadIdx.x >> 5] = a;
    }
    __syncthreads();
    if (threadIdx.x < 4) {
        int r = threadIdx.x;
        float a = 0.f;
        #pragma unroll
        for (int w = 0; w < NT/32; w++) a += sred[r][w];
        out[row0 + r] = a + b[row0 + r];
    }
}

// ---------------- final: inorm(512) -> leaky -> softmax(512), 3 blocks ----------------
__device__ __forceinline__ float blk_sum512(float v, volatile float* sh) {
    int t = threadIdx.x;
    #pragma unroll
    for (int o = 16; o > 0; o >>= 1) v += __shfl_xor_sync(0xffffffffu, v, o);
    if ((t & 31) == 0) sh[t >> 5] = v;
    __syncthreads();
    if (t == 0) {
        float a = 0.f;
        #pragma unroll
        for (int w = 0; w < 16; w++) a += sh[w];
        sh[16] = a;
    }
    __syncthreads();
    float r = sh[16];
    __syncthreads();
    return r;
}

__device__ __forceinline__ float blk_max512(float v, volatile float* sh) {
    int t = threadIdx.x;
    #pragma unroll
    for (int o = 16; o > 0; o >>= 1) v = fmaxf(v, __shfl_xor_sync(0xffffffffu, v, o));
    if ((t & 31) == 0) sh[t >> 5] = v;
    __syncthreads();
    if (t == 0) {
        float a = -3.4e38f;
        #pragma unroll
        for (int w = 0; w < 16; w++) a = fmaxf(a, sh[w]);
        sh[16] = a;
    }
    __syncthreads();
    float r = sh[16];
    __syncthreads();
    return r;
}

__global__ __launch_bounds__(512) void k_final(float* __restrict__ out) {
    __shared__ float sh[17];
    int b = blockIdx.x;   // 0..2
    int t = threadIdx.x;  // 0..511
    float v = g_o[b*SYM + t];
    float sum = blk_sum512(v, sh);
    float sq  = blk_sum512(v*v, sh);
    float m = sum * (1.0f/SYM);
    float var = sq * (1.0f/SYM) - m*m;
    float xn = (v - m) * rsqrtf(var + EPSF);
    xn = (xn >= 0.f) ? xn : 0.01f*xn;
    float mx = blk_max512(xn, sh);
    float e = expf(xn - mx);
    float se = blk_sum512(e, sh);
    out[b*SYM + t] = e / se;
}

// ---------------- launch ----------------
extern "C" void kernel_launch(void* const* d_in, const int* in_sizes, int n_in,
                              void* d_out, int out_size) {
    const float* wax   = (const float*)d_in[0];
    const float* blw   = (const float*)d_in[1];
    const float* blb   = (const float*)d_in[2];
    const float* w_ih0 = (const float*)d_in[3];
    // d_in[4] = w_hh0 (unused: h0 = 0)
    const float* b_ih0 = (const float*)d_in[5];
    const float* b_hh0 = (const float*)d_in[6];
    const float* w_ih1 = (const float*)d_in[7];
    const float* b_ih1 = (const float*)d_in[9];
    const float* b_hh1 = (const float*)d_in[10];
    const float* w_ih2 = (const float*)d_in[11];
    const float* b_ih2 = (const float*)d_in[13];
    const float* b_hh2 = (const float*)d_in[14];
    const float* lin_w = (const float*)d_in[15];
    const float* lin_b = (const float*)d_in[16];
    float* out = (float*)d_out;

    static float *p_v = nullptr, *p_gates = nullptr, *p_h = nullptr, *p_o = nullptr;
    if (!p_v) {
        cudaGetSymbolAddress((void**)&p_v,     g_v);
        cudaGetSymbolAddress((void**)&p_gates, g_gates);
        cudaGetSymbolAddress((void**)&p_h,     g_h);
        cudaGetSymbolAddress((void**)&p_o,     g_o);
    }

    k_front<<<SYM, 128>>>(wax, blw, blb);

    // cell 0: HIN -> H
    k_gates4<256><<<(3*HH)/4, 256>>>(w_ih0, p_v, b_ih0, b_hh0, p_gates, HIN);
    k_act<<<HH/256, 256>>>(p_gates, p_h);

    // cell 1: H -> H
    k_gates4<128><<<(3*HH)/4, 128>>>(w_ih1, p_h, b_ih1, b_hh1, p_gates, HH);
    k_act<<<HH/256, 256>>>(p_gates, p_h);

    // cell 2: H -> H
    k_gates4<128><<<(3*HH)/4, 128>>>(w_ih2, p_h, b_ih2, b_hh2, p_gates, HH);
    k_act<<<HH/256, 256>>>(p_gates, p_h);

    // linear head + finalize
    k_lin4<128><<<NO/4, 128>>>(lin_w, p_h, lin_b, p_o, HH);
    k_final<<<NS, 512>>>(out);
}

// round 2
// speedup vs baseline: 1.1352x; 1.1352x over previous
#include <cuda_runtime.h>
#include <math.h>

#define NS 3
#define SYM 512
#define FD 20
#define NLIN 11
#define NOUT 9
#define HH 2048
#define HIN (NS*SYM*NOUT)   /* 13824 */
#define NO (NS*SYM)         /* 1536 */
#define EPSF 1e-9f

// ---------------- device scratch (no allocations allowed) ----------------
__device__ float g_v[HIN];
__device__ float g_h[HH];
__device__ float g_o[NO];

// ---------------- front end: inorm -> DFT -> bilinear -> leaky -> softmax(NS) ----------------
__global__ __launch_bounds__(128) void k_front(const float* __restrict__ wax,
                                               const float* __restrict__ blw,
                                               const float* __restrict__ blb) {
    int s = blockIdx.x;           // 0..511
    int tid = threadIdx.x;
    int warp = tid >> 5, lane = tid & 31;

    __shared__ float sh_xn[NS][FD];
    __shared__ float sh_re[NS][NLIN], sh_im[NS][NLIN];
    __shared__ float sh_z[NS][NOUT];

    if (warp < NS) {
        int b = warp;
        float x = 0.f;
        if (lane < FD) x = wax[(b*SYM + s)*FD + lane];
        float sum = x, sq = x*x;
        #pragma unroll
        for (int o = 16; o > 0; o >>= 1) {
            sum += __shfl_xor_sync(0xffffffffu, sum, o);
            sq  += __shfl_xor_sync(0xffffffffu, sq,  o);
        }
        float m = sum * (1.0f/FD);
        float var = sq * (1.0f/FD) - m*m;
        float r = rsqrtf(var + EPSF);
        if (lane < FD) sh_xn[b][lane] = (x - m) * r;
        __syncwarp();

        if (lane < NLIN) {
            float re = 0.f, im = 0.f;
            #pragma unroll
            for (int f = 0; f < FD; f++) {
                float sn, cs;
                sincospif((float)(lane*f) * 0.1f, &sn, &cs); // 2*pi*k*f/20 = pi*(k*f/10)
                float xv = sh_xn[b][f];
                re += xv * cs;
                im -= xv * sn;
            }
            sh_re[b][lane] = re;
            sh_im[b][lane] = im;
        }
        __syncwarp();

        if (lane < NOUT) {
            int k = lane;
            float z = blb[k];
            #pragma unroll
            for (int i = 0; i < NLIN; i++) {
                float t = 0.f;
                #pragma unroll
                for (int j = 0; j < NLIN; j++)
                    t += blw[(k*NLIN + i)*NLIN + j] * sh_im[b][j];
                z += sh_re[b][i] * t;
            }
            z = (z >= 0.f) ? z : 0.01f*z;   // leaky_relu
            sh_z[b][k] = z;
        }
    }
    __syncthreads();

    if (tid < NOUT) {
        int k = tid;
        float z0 = sh_z[0][k], z1 = sh_z[1][k], z2 = sh_z[2][k];
        float m = fmaxf(z0, fmaxf(z1, z2));
        float e0 = expf(z0-m), e1 = expf(z1-m), e2 = expf(z2-m);
        float inv = 1.f/(e0+e1+e2);
        g_v[s*(NS*NOUT) + 0*NOUT + k] = e0*inv;
        g_v[s*(NS*NOUT) + 1*NOUT + k] = e1*inv;
        g_v[s*(NS*NOUT) + 2*NOUT + k] = e2*inv;
    }
}

// ---------------- fused LSTM cell (zero state): gates i,g,o for same j + activation ----------------
// Block computes h[j0 .. j0+JPB-1] directly. f-gate skipped (c0 = 0).
template<int NT, int N, int JPB>
__global__ __launch_bounds__(NT) void k_cell(const float* __restrict__ W,
                                             const float* __restrict__ x,
                                             const float* __restrict__ b_ih,
                                             const float* __restrict__ b_hh,
                                             float* __restrict__ h) {
    constexpr int N4   = N / 4;
    constexpr int ITER = N4 / NT;       // exact division by construction
    constexpr int NR   = 3 * JPB;
    const int j0 = blockIdx.x * JPB;
    const int tid = threadIdx.x;

    const float4* __restrict__ xv = (const float4*)x;
    const float4* Wr[NR];
    #pragma unroll
    for (int q = 0; q < JPB; q++) {
        int j = j0 + q;
        Wr[3*q + 0] = (const float4*)(W + (size_t)(0*HH + j) * N);  // i
        Wr[3*q + 1] = (const float4*)(W + (size_t)(2*HH + j) * N);  // g
        Wr[3*q + 2] = (const float4*)(W + (size_t)(3*HH + j) * N);  // o
    }

    float acc[NR];
    #pragma unroll
    for (int r = 0; r < NR; r++) acc[r] = 0.f;

    #pragma unroll 6
    for (int it = 0; it < ITER; it++) {
        int t = tid + it * NT;
        float4 v = xv[t];
        #pragma unroll
        for (int r = 0; r < NR; r++) {
            float4 w = __ldcs(&Wr[r][t]);
            acc[r] += w.x*v.x + w.y*v.y + w.z*v.z + w.w*v.w;
        }
    }

    __shared__ float sred[NR][NT/32];
    #pragma unroll
    for (int r = 0; r < NR; r++) {
        float a = acc[r];
        #pragma unroll
        for (int o = 16; o > 0; o >>= 1) a += __shfl_xor_sync(0xffffffffu, a, o);
        if ((tid & 31) == 0) sred[r][tid >> 5] = a;
    }
    __syncthreads();

    if (tid < JPB) {
        int q = tid, j = j0 + q;
        float gi = 0.f, gg = 0.f, go = 0.f;
        #pragma unroll
        for (int w = 0; w < NT/32; w++) {
            gi += sred[3*q + 0][w];
            gg += sred[3*q + 1][w];
            go += sred[3*q + 2][w];
        }
        gi += b_ih[j]        + b_hh[j];
        gg += b_ih[2*HH + j] + b_hh[2*HH + j];
        go += b_ih[3*HH + j] + b_hh[3*HH + j];
        float si = 1.f / (1.f + __expf(-gi));
        float so = 1.f / (1.f + __expf(-go));
        float c  = si * tanhf(gg);
        h[j] = so * tanhf(c);
    }
}

// ---------------- linear head: 4 rows per block, compile-time N ----------------
template<int NT, int N>
__global__ __launch_bounds__(NT) void k_lin4(const float* __restrict__ W,
                                             const float* __restrict__ x,
                                             const float* __restrict__ b,
                                             float* __restrict__ out) {
    constexpr int N4   = N / 4;
    constexpr int ITER = N4 / NT;
    const int row0 = blockIdx.x * 4;
    const int tid = threadIdx.x;
    const float4* __restrict__ xv = (const float4*)x;

    const float4* Wr[4];
    #pragma unroll
    for (int r = 0; r < 4; r++)
        Wr[r] = (const float4*)(W + (size_t)(row0 + r) * N);

    float acc[4] = {0.f, 0.f, 0.f, 0.f};
    #pragma unroll
    for (int it = 0; it < ITER; it++) {
        int t = tid + it * NT;
        float4 v = xv[t];
        #pragma unroll
        for (int r = 0; r < 4; r++) {
            float4 w = __ldcs(&Wr[r][t]);
            acc[r] += w.x*v.x + w.y*v.y + w.z*v.z + w.w*v.w;
        }
    }

    __shared__ float sred[4][NT/32];
    #pragma unroll
    for (int r = 0; r < 4; r++) {
        float a = acc[r];
        #pragma unroll
        for (int o = 16; o > 0; o >>= 1) a += __shfl_xor_sync(0xffffffffu, a, o);
        if ((tid & 31) == 0) sred[r][tid >> 5] = a;
    }
    __syncthreads();
    if (tid < 4) {
        int r = tid;
        float a = 0.f;
        #pragma unroll
        for (int w = 0; w < NT/32; w++) a += sred[r][w];
        out[row0 + r] = a + b[row0 + r];
    }
}

// ---------------- final: inorm(512) -> leaky -> softmax(512), 3 blocks ----------------
__device__ __forceinline__ float blk_sum512(float v, volatile float* sh) {
    int t = threadIdx.x;
    #pragma unroll
    for (int o = 16; o > 0; o >>= 1) v += __shfl_xor_sync(0xffffffffu, v, o);
    if ((t & 31) == 0) sh[t >> 5] = v;
    __syncthreads();
    if (t == 0) {
        float a = 0.f;
        #pragma unroll
        for (int w = 0; w < 16; w++) a += sh[w];
        sh[16] = a;
    }
    __syncthreads();
    float r = sh[16];
    __syncthreads();
    return r;
}

__device__ __forceinline__ float blk_max512(float v, volatile float* sh) {
    int t = threadIdx.x;
    #pragma unroll
    for (int o = 16; o > 0; o >>= 1) v = fmaxf(v, __shfl_xor_sync(0xffffffffu, v, o));
    if ((t & 31) == 0) sh[t >> 5] = v;
    __syncthreads();
    if (t == 0) {
        float a = -3.4e38f;
        #pragma unroll
        for (int w = 0; w < 16; w++) a = fmaxf(a, sh[w]);
        sh[16] = a;
    }
    __syncthreads();
    float r = sh[16];
    __syncthreads();
    return r;
}

__global__ __launch_bounds__(512) void k_final(float* __restrict__ out) {
    __shared__ float sh[17];
    int b = blockIdx.x;   // 0..2
    int t = threadIdx.x;  // 0..511
    float v = g_o[b*SYM + t];
    float sum = blk_sum512(v, sh);
    float sq  = blk_sum512(v*v, sh);
    float m = sum * (1.0f/SYM);
    float var = sq * (1.0f/SYM) - m*m;
    float xn = (v - m) * rsqrtf(var + EPSF);
    xn = (xn >= 0.f) ? xn : 0.01f*xn;
    float mx = blk_max512(xn, sh);
    float e = expf(xn - mx);
    float se = blk_sum512(e, sh);
    out[b*SYM + t] = e / se;
}

// ---------------- launch ----------------
extern "C" void kernel_launch(void* const* d_in, const int* in_sizes, int n_in,
                              void* d_out, int out_size) {
    const float* wax   = (const float*)d_in[0];
    const float* blw   = (const float*)d_in[1];
    const float* blb   = (const float*)d_in[2];
    const float* w_ih0 = (const float*)d_in[3];
    // d_in[4] = w_hh0 (unused: h0 = 0)
    const float* b_ih0 = (const float*)d_in[5];
    const float* b_hh0 = (const float*)d_in[6];
    const float* w_ih1 = (const float*)d_in[7];
    const float* b_ih1 = (const float*)d_in[9];
    const float* b_hh1 = (const float*)d_in[10];
    const float* w_ih2 = (const float*)d_in[11];
    const float* b_ih2 = (const float*)d_in[13];
    const float* b_hh2 = (const float*)d_in[14];
    const float* lin_w = (const float*)d_in[15];
    const float* lin_b = (const float*)d_in[16];
    float* out = (float*)d_out;

    static float *p_v = nullptr, *p_h = nullptr, *p_o = nullptr;
    if (!p_v) {
        cudaGetSymbolAddress((void**)&p_v, g_v);
        cudaGetSymbolAddress((void**)&p_h, g_h);
        cudaGetSymbolAddress((void**)&p_o, g_o);
    }

    k_front<<<SYM, 128>>>(wax, blw, blb);

    // cell 0: HIN=13824 -> H. N4=3456, NT=192 -> 18 iters, 1 j per block (3 rows)
    k_cell<192, HIN, 1><<<HH/1, 192>>>(w_ih0, p_v, b_ih0, b_hh0, p_h);

    // cells 1,2: H -> H. N4=512, NT=128 -> 4 iters, 2 j per block (6 rows)
    k_cell<128, HH, 2><<<HH/2, 128>>>(w_ih1, p_h, b_ih1, b_hh1, p_h);
    k_cell<128, HH, 2><<<HH/2, 128>>>(w_ih2, p_h, b_ih2, b_hh2, p_h);

    // linear head + finalize
    k_lin4<128, HH><<<NO/4, 128>>>(lin_w, p_h, lin_b, p_o);
    k_final<<<NS, 512>>>(out);
}